// round 8
// baseline (speedup 1.0000x reference)
#include <cuda_runtime.h>

// SortPool2D: x (16,224,224,256) fp32 NHWC -> out (16,112,112,256)
// Sort 2x2 spatial values ascending, dot with softmax(pool_weights[4]).
// Pure HBM-bound stream: 822MB in + 205MB out. Optimize stream efficiency:
// 2 outputs/thread (MLP=8), evict-first cache hints, halved index math.

#define B_DIM    16
#define H_IN     224
#define W_IN     224
#define C_DIM    256
#define H_OUT    (H_IN / 2)     // 112
#define W_OUT    (W_IN / 2)     // 112
#define C4       (C_DIM / 4)    // 64 float4 per pixel
#define IN_ROW4  (W_IN * C4)    // 14336 float4 per input row
#define PIX_OUT  (B_DIM * H_OUT * W_OUT)   // 200704 output pixels
// Each thread handles one (pixel, half) pair: 2 float4 at c4 and c4+32.
#define NTHREADS (PIX_OUT * 32)            // 6,422,528

__device__ __forceinline__ float sort4_dot(float a, float b, float c, float d,
                                           float w0, float w1, float w2, float w3) {
    float lo0 = fminf(a, b), hi0 = fmaxf(a, b);
    float lo1 = fminf(c, d), hi1 = fmaxf(c, d);
    float s0  = fminf(lo0, lo1);
    float t0  = fmaxf(lo0, lo1);
    float t1  = fminf(hi0, hi1);
    float s3  = fmaxf(hi0, hi1);
    float s1  = fminf(t0, t1);
    float s2  = fmaxf(t0, t1);
    return fmaf(s0, w0, fmaf(s1, w1, fmaf(s2, w2, s3 * w3)));
}

__device__ __forceinline__ float4 blend4(float4 v00, float4 v01, float4 v10, float4 v11,
                                         float w0, float w1, float w2, float w3) {
    float4 r;
    r.x = sort4_dot(v00.x, v01.x, v10.x, v11.x, w0, w1, w2, w3);
    r.y = sort4_dot(v00.y, v01.y, v10.y, v11.y, w0, w1, w2, w3);
    r.z = sort4_dot(v00.z, v01.z, v10.z, v11.z, w0, w1, w2, w3);
    r.w = sort4_dot(v00.w, v01.w, v10.w, v11.w, w0, w1, w2, w3);
    return r;
}

__global__ void __launch_bounds__(256)
sortpool2d_kernel(const float4* __restrict__ x,
                  const float*  __restrict__ pw,
                  float4*       __restrict__ out) {
    __shared__ float w[4];
    if (threadIdx.x == 0) {
        float a0 = pw[0], a1 = pw[1], a2 = pw[2], a3 = pw[3];
        float m  = fmaxf(fmaxf(a0, a1), fmaxf(a2, a3));
        float e0 = __expf(a0 - m), e1 = __expf(a1 - m);
        float e2 = __expf(a2 - m), e3 = __expf(a3 - m);
        float inv = 1.0f / (e0 + e1 + e2 + e3);
        w[0] = e0 * inv; w[1] = e1 * inv; w[2] = e2 * inv; w[3] = e3 * inv;
    }
    __syncthreads();
    float w0 = w[0], w1 = w[1], w2 = w[2], w3 = w[3];

    unsigned t = blockIdx.x * blockDim.x + threadIdx.x;
    if (t >= NTHREADS) return;

    // t -> (pixel, lane-phase). Lane phase = t & 31 keeps warp coalesced.
    unsigned c4 = t & 31u;            // first half-channel index (0..31)
    unsigned p  = t >> 5;             // output pixel index (b*H_OUT+h)*W_OUT+wo
    unsigned wo = p % W_OUT;
    unsigned bh = p / W_OUT;          // b*H_OUT + h
    unsigned h  = bh % H_OUT;
    unsigned b  = bh / H_OUT;

    long base = ((long)(b * H_IN + 2u * h) * W_IN + 2u * wo) * C4 + c4;
    long obase = (long)p * C4 + c4;

    // 8 independent loads (MLP=8), all evict-first streaming.
    float4 a00 = __ldcs(&x[base]);
    float4 a01 = __ldcs(&x[base + C4]);
    float4 a10 = __ldcs(&x[base + IN_ROW4]);
    float4 a11 = __ldcs(&x[base + IN_ROW4 + C4]);
    float4 b00 = __ldcs(&x[base + 32]);
    float4 b01 = __ldcs(&x[base + C4 + 32]);
    float4 b10 = __ldcs(&x[base + IN_ROW4 + 32]);
    float4 b11 = __ldcs(&x[base + IN_ROW4 + C4 + 32]);

    float4 r0 = blend4(a00, a01, a10, a11, w0, w1, w2, w3);
    float4 r1 = blend4(b00, b01, b10, b11, w0, w1, w2, w3);

    __stcs(&out[obase],      r0);
    __stcs(&out[obase + 32], r1);
}

extern "C" void kernel_launch(void* const* d_in, const int* in_sizes, int n_in,
                              void* d_out, int out_size) {
    const float4* x  = (const float4*)d_in[0];
    const float*  pw = (const float*)d_in[1];
    float4*       o  = (float4*)d_out;

    int blocks = (NTHREADS + 255) / 256;  // 25088, NTHREADS divisible by 256
    sortpool2d_kernel<<<blocks, 256>>>(x, pw, o);
}